// round 15
// baseline (speedup 1.0000x reference)
#include <cuda_runtime.h>
#include <cuda_bf16.h>
#include <math.h>
#include <stdint.h>

#define BATCH 32
#define CDIM  512
#define NDIM  4096
#define TCL   72
#define KCL   64
#define NT1   128
#define NTILES 32            // 4096/128

// Scratch (static device globals; no runtime allocation)
__device__ __nv_bfloat16 g_wb[16 * 80 * 32];   // W bf16 [chunk16][t(80)][c(32)]
__device__ float g_massp[(size_t)BATCH * NTILES * KCL];
__device__ float g_aggp[(size_t)NTILES * BATCH * KCL * CDIM];  // split-K partials

__device__ __forceinline__ unsigned smem_u32(const void* p) {
    unsigned a;
    asm("{ .reg .u64 t; cvta.to.shared.u64 t, %1; cvt.u32.u64 %0, t; }" : "=r"(a) : "l"(p));
    return a;
}
__device__ __forceinline__ void ldsm_x4(uint32_t* r, unsigned addr) {
    asm volatile("ldmatrix.sync.aligned.m8n8.x4.shared.b16 {%0,%1,%2,%3}, [%4];"
                 : "=r"(r[0]), "=r"(r[1]), "=r"(r[2]), "=r"(r[3]) : "r"(addr));
}
__device__ __forceinline__ void ldsm_x4t(uint32_t* r, unsigned addr) {
    asm volatile("ldmatrix.sync.aligned.m8n8.x4.trans.shared.b16 {%0,%1,%2,%3}, [%4];"
                 : "=r"(r[0]), "=r"(r[1]), "=r"(r[2]), "=r"(r[3]) : "r"(addr));
}
__device__ __forceinline__ void mma_bf16(float* c, const uint32_t* a, const uint32_t* b) {
    asm volatile(
        "mma.sync.aligned.m16n8k16.row.col.f32.bf16.bf16.f32 "
        "{%0,%1,%2,%3},{%4,%5,%6,%7},{%8,%9},{%0,%1,%2,%3};"
        : "+f"(c[0]), "+f"(c[1]), "+f"(c[2]), "+f"(c[3])
        : "r"(a[0]), "r"(a[1]), "r"(a[2]), "r"(a[3]), "r"(b[0]), "r"(b[1]));
}
__device__ __forceinline__ void sts_v2(unsigned addr, __nv_bfloat162 p0, __nv_bfloat162 p1) {
    asm volatile("st.shared.v2.b32 [%0], {%1,%2};"
                 :: "r"(addr), "r"(*(unsigned*)&p0), "r"(*(unsigned*)&p1));
}
__device__ __forceinline__ void cpa16(unsigned dst, const void* src) {
    asm volatile("cp.async.cg.shared.global [%0], [%1], 16;" :: "r"(dst), "l"(src));
}
#define CP_COMMIT() asm volatile("cp.async.commit_group;")

// ---------------------------------------------------------------------------
// Pass 0w: W fp32 -> bf16 table [16 chunks][80 t][32 c] (tiny; grid 1)
// ---------------------------------------------------------------------------
__global__ __launch_bounds__(256) void pass0w(const float* __restrict__ conv_w)
{
    const int tid = threadIdx.x;
    for (int i = tid; i < 80 * 512; i += 256) {
        int t = i >> 9, c = i & 511;
        float v = (t < TCL) ? conv_w[t * CDIM + c] : 0.0f;
        g_wb[(c >> 5) * 2560 + t * 32 + (c & 31)] = __float2bfloat16(v);
    }
}

// ---------------------------------------------------------------------------
// Megapass: per (ntile, b) block —
//  Phase A (16 chunks, 4-stage cp.async): fp32 x -> ssq + bf16 xb (RESIDENT,
//    512c x 128n, 256B rows swz>>4) + GEMM1 logits (HMMA vs W-in-ring).
//  Phase B: invn, logits, softmax, a2 (smem, swizzled), mass partials.
//  Phase C: GEMM2  aggp[k,c] = sum_n xb[c,n]*a2[k,n]  (8 warps x 64c x 64k),
//    staged through xb region (dead) for coalesced 128KB fp32 write.
// ---------------------------------------------------------------------------
#define MP_XB    0u           // 512c x 128n bf16, 256B rows, swz>>4 (131072B)
#define MP_RING  131072u      // 4 stages x 23040 (x fp32 16384 + W 6656)
#define MP_STG   23040u
#define MP_WOFF  16384u
#define MP_LG    131072u      // phase B alias: [128 n][84 t] fp32 (43008B)
#define MP_A2ST  174080u      // [64 k][128 n] bf16, 256B rows swz>>4 (16384B)
#define MP_BIAS  223232u      // 80 fp32 (outside ring: live during phase A)
#define MP_SSQS  223552u      // 4KB scratch (ssq partials / mass partials)
#define MP_INVN  227648u      // 128 fp32
#define MP_SMEM  228160

__global__ __launch_bounds__(256) void megapass(const float* __restrict__ x,
                                                const float* __restrict__ conv_b)
{
    extern __shared__ char sm[];
    const unsigned sb = smem_u32(sm);
    const int ntile = blockIdx.x;
    const int b     = blockIdx.y;
    const int n0    = ntile * NT1;
    const int tid   = threadIdx.x;
    const int lane  = tid & 31;
    const int wid   = tid >> 5;
    const int m0    = wid * 16;       // GEMM1 n-slice

    if (tid < 80) {
        float v = (tid < TCL) ? conv_b[tid] : 0.0f;
        *(float*)(sm + MP_BIAS + tid * 4) = v;
    }

    const float* xsrc = x + (size_t)b * CDIM * NDIM + n0;

#define MP_ISSUE(ST, CH) do {                                                  \
        unsigned _buf = sb + MP_RING + (unsigned)(ST) * MP_STG;                \
        const float* _xs = xsrc + (size_t)(CH) * 32 * NDIM;                    \
        _Pragma("unroll")                                                      \
        for (int r = 0; r < 4; r++) {                                          \
            int idx = tid + 256 * r;                                           \
            int c = idx >> 5, q = idx & 31;                                    \
            cpa16(_buf + (unsigned)(c * 512 + q * 16),                         \
                  _xs + (size_t)c * NDIM + 4 * q);                             \
        }                                                                      \
        const __nv_bfloat16* _ws = g_wb + (CH) * 2560;                         \
        _Pragma("unroll")                                                      \
        for (int r = 0; r < 2; r++) {                                          \
            int idx = tid + 256 * r;                                           \
            if (idx < 320) {                                                   \
                int t = idx >> 2, pc = idx & 3;                                \
                cpa16(_buf + MP_WOFF + (unsigned)(t * 80 + pc * 16),           \
                      _ws + t * 32 + pc * 8);                                  \
            }                                                                  \
        }                                                                      \
    } while (0)

    MP_ISSUE(0, 0); CP_COMMIT();
    MP_ISSUE(1, 1); CP_COMMIT();
    MP_ISSUE(2, 2); CP_COMMIT();

    float acc[10][4];
    #pragma unroll
    for (int i = 0; i < 10; i++)
        #pragma unroll
        for (int j = 0; j < 4; j++) acc[i][j] = 0.0f;
    float ssq4[4] = {0.f, 0.f, 0.f, 0.f};

    const int cg = tid >> 5;       // 0..7 (4 c rows each)
    const int gq = tid & 31;       // float4 column (4 n)

    // ================= Phase A: convert + GEMM1 =============================
    for (int ch = 0; ch < 16; ch++) {
        asm volatile("cp.async.wait_group 2;" ::: "memory");
        __syncthreads();
        if (ch + 3 < 16) MP_ISSUE((ch + 3) & 3, ch + 3);
        CP_COMMIT();

        // convert: fp32 stage -> ssq + bf16 into resident xb rows ch*32..+32
        {
            const char* stg = sm + MP_RING + (unsigned)(ch & 3) * MP_STG;
            #pragma unroll
            for (int r = 0; r < 4; r++) {
                int c = cg * 4 + r;
                float4 v = *(const float4*)(stg + c * 512 + gq * 16);
                ssq4[0] = fmaf(v.x, v.x, ssq4[0]);
                ssq4[1] = fmaf(v.y, v.y, ssq4[1]);
                ssq4[2] = fmaf(v.z, v.z, ssq4[2]);
                ssq4[3] = fmaf(v.w, v.w, ssq4[3]);
                __nv_bfloat162 h01 = __floats2bfloat162_rn(v.x, v.y);
                __nv_bfloat162 h23 = __floats2bfloat162_rn(v.z, v.w);
                unsigned off = (unsigned)((ch * 32 + c) * 256 + gq * 8);
                sts_v2(sb + MP_XB + (off ^ ((off >> 4) & 0x70)), h01, h23);
            }
        }
        __syncthreads();

        // GEMM1: logits MMA — A^T from xb (trans), B = W tile (80B rows)
        const unsigned wst = sb + MP_RING + (unsigned)(ch & 3) * MP_STG + MP_WOFF;
        #pragma unroll
        for (int ks = 0; ks < 2; ks++) {
            uint32_t a[4];
            {
                int crow = ch * 32 + ks * 16 + (lane & 7) + ((lane >> 4) & 1) * 8;
                int ncol = m0 + ((lane >> 3) & 1) * 8;
                unsigned off = (unsigned)(crow * 256 + ncol * 2);
                ldsm_x4t(a, sb + MP_XB + (off ^ ((off >> 4) & 0x70)));
            }
            #pragma unroll
            for (int nb = 0; nb < 5; nb++) {
                uint32_t bf[4];
                int trow = nb * 16 + ((lane >> 4) & 1) * 8 + (lane & 7);
                unsigned addr = wst + (unsigned)(trow * 80 + ks * 32
                                                 + ((lane >> 3) & 1) * 16);
                ldsm_x4(bf, addr);
                mma_bf16(acc[2 * nb],     a, &bf[0]);
                mma_bf16(acc[2 * nb + 1], a, &bf[2]);
            }
        }
    }

    // ================= Phase B: invn, logits, softmax, a2, mass =============
    *(float4*)(sm + MP_SSQS + (unsigned)tid * 16) =
        make_float4(ssq4[0], ssq4[1], ssq4[2], ssq4[3]);
    __syncthreads();
    if (tid < 128) {
        const float* fs = (const float*)(sm + MP_SSQS);
        float s = 0.0f;
        #pragma unroll
        for (int w2 = 0; w2 < 8; w2++) s += fs[w2 * 128 + tid];
        ((float*)(sm + MP_INVN))[tid] = 1.0f / fmaxf(sqrtf(s), 1e-12f);
    }
    __syncthreads();

    {   // fragments -> logits smem [128 n][84 t]  (ring region, now dead)
        float* lg = (float*)(sm + MP_LG);
        const float* invn = (const float*)(sm + MP_INVN);
        const float* bias = (const float*)(sm + MP_BIAS);
        int r0 = m0 + (lane >> 2);
        float i0 = invn[r0], i1 = invn[r0 + 8];
        #pragma unroll
        for (int nb = 0; nb < 10; nb++) {
            int tc = nb * 8 + 2 * (lane & 3);
            float b0 = bias[tc], b1 = bias[tc + 1];
            lg[r0 * 84 + tc]           = acc[nb][0] * i0 + b0;
            lg[r0 * 84 + tc + 1]       = acc[nb][1] * i0 + b1;
            lg[(r0 + 8) * 84 + tc]     = acc[nb][2] * i1 + b0;
            lg[(r0 + 8) * 84 + tc + 1] = acc[nb][3] * i1 + b1;
        }
    }
    __syncthreads();

    // softmax per n; a2 bf16 -> A2ST ([64k][128n], 256B rows, swz>>4)
    if (tid < 128) {
        float* row = (float*)(sm + MP_LG) + tid * 84;
        float invn_n = ((float*)(sm + MP_INVN))[tid];
        float mx = -1e30f;
        #pragma unroll 8
        for (int t = 0; t < TCL; t++) mx = fmaxf(mx, row[t]);
        float s = 0.0f;
        #pragma unroll 8
        for (int t = 0; t < TCL; t++) { float e = __expf(row[t] - mx); row[t] = e; s += e; }
        float inv_s = 1.0f / s;
        float a2s   = inv_s * invn_n;
        #pragma unroll 8
        for (int t = 0; t < KCL; t++) {
            float e = row[t];
            unsigned off = (unsigned)(t * 256 + 2 * tid);
            *(__nv_bfloat16*)(sm + MP_A2ST + (off ^ ((off >> 4) & 0x70)))
                = __float2bfloat16(e * a2s);
            row[t] = e * inv_s;
        }
    }
    __syncthreads();

    // mass partials (parallel, deterministic): k = tid&63, part = tid>>6
    {
        float* mp = (float*)(sm + MP_SSQS);
        const float* lg = (const float*)(sm + MP_LG);
        const int k = tid & 63, part = tid >> 6;
        float m = 0.0f;
        #pragma unroll 8
        for (int n = 0; n < 32; n++) m += lg[(part * 32 + n) * 84 + k];
        mp[part * 64 + k] = m;
    }
    __syncthreads();
    if (tid < KCL) {
        const float* mp = (const float*)(sm + MP_SSQS);
        g_massp[((size_t)b * NTILES + ntile) * KCL + tid] =
            mp[tid] + mp[64 + tid] + mp[128 + tid] + mp[192 + tid];
    }

    // ================= Phase C: GEMM2 (partial agg) =========================
    // D[c,k] = sum_n xb[c,n] * a2[k,n]; warp tile 64c x 64k, K = 128 n.
    const int wm = wid * 64;
    float ag[4][8][4];
    #pragma unroll
    for (int mf = 0; mf < 4; mf++)
        #pragma unroll
        for (int nf = 0; nf < 8; nf++)
            #pragma unroll
            for (int q = 0; q < 4; q++) ag[mf][nf][q] = 0.0f;

    #pragma unroll
    for (int ks = 0; ks < 8; ks++) {
        uint32_t a[4][4], bh[4][4];
        #pragma unroll
        for (int mf = 0; mf < 4; mf++) {
            unsigned off = (unsigned)((wm + mf * 16 + (lane & 15)) * 256
                                      + ks * 32 + (lane >> 4) * 16);
            ldsm_x4(a[mf], sb + MP_XB + (off ^ ((off >> 4) & 0x70)));
        }
        #pragma unroll
        for (int kg = 0; kg < 4; kg++) {
            unsigned off = (unsigned)((kg * 16 + (lane >> 4) * 8 + (lane & 7)) * 256
                                      + ks * 32 + ((lane >> 3) & 1) * 16);
            ldsm_x4(bh[kg], sb + MP_A2ST + (off ^ ((off >> 4) & 0x70)));
        }
        #pragma unroll
        for (int mf = 0; mf < 4; mf++)
            #pragma unroll
            for (int kg = 0; kg < 4; kg++)
                #pragma unroll
                for (int h = 0; h < 2; h++)
                    mma_bf16(ag[mf][kg * 2 + h], a[mf], &bh[kg][2 * h]);
    }
    __syncthreads();   // xb reads complete everywhere before overwriting as agg

    // fragments -> agg staging [64 k][512 c] fp32 in XB region
    {
        float* ags = (float*)(sm + MP_XB);
        #pragma unroll
        for (int mf = 0; mf < 4; mf++) {
            int c = wm + mf * 16 + (lane >> 2);
            #pragma unroll
            for (int nf = 0; nf < 8; nf++) {
                int k = nf * 8 + (lane & 3) * 2;
                ags[k * 512 + c]           = ag[mf][nf][0];
                ags[(k + 1) * 512 + c]     = ag[mf][nf][1];
                ags[k * 512 + c + 8]       = ag[mf][nf][2];
                ags[(k + 1) * 512 + c + 8] = ag[mf][nf][3];
            }
        }
    }
    __syncthreads();

    // coalesced partial writeout: 128KB fp32
    {
        float* dst = g_aggp + ((size_t)ntile * BATCH + b) * KCL * CDIM;
        const float4* src = (const float4*)(sm + MP_XB);
        #pragma unroll
        for (int it = 0; it < 32; it++) {
            int idx = tid + 256 * it;
            ((float4*)dst)[idx] = src[idx];
        }
    }
#undef MP_ISSUE
}

// ---------------------------------------------------------------------------
// Pass 3: v = sum_nt aggp - centroid*mass; out = v/(max(||v||,eps)*8)
// (attention, ghost weighting and global norm cancel algebraically)
// ---------------------------------------------------------------------------
__global__ __launch_bounds__(128) void pass3(const float* __restrict__ centroids,
                                             float* __restrict__ out)
{
    const int k   = blockIdx.x;
    const int b   = blockIdx.y;
    const int tid = threadIdx.x;

    __shared__ float s_mass;
    __shared__ float s_red[4];

    if (tid == 0) {
        float m = 0.0f;
        #pragma unroll
        for (int t = 0; t < NTILES; t++) m += g_massp[((size_t)b * NTILES + t) * KCL + k];
        s_mass = m;
    }
    __syncthreads();
    const float mass = s_mass;

    float v[4];
    float ssq = 0.0f;
    #pragma unroll
    for (int j = 0; j < 4; j++) {
        int c = tid + 128 * j;
        float a = 0.0f;
        #pragma unroll
        for (int nt = 0; nt < NTILES; nt++)
            a += g_aggp[(((size_t)nt * BATCH + b) * KCL + k) * CDIM + c];
        float val = a - centroids[k * CDIM + c] * mass;
        v[j] = val;
        ssq = fmaf(val, val, ssq);
    }
    #pragma unroll
    for (int o = 16; o > 0; o >>= 1) ssq += __shfl_xor_sync(0xffffffffu, ssq, o);
    if ((tid & 31) == 0) s_red[tid >> 5] = ssq;
    __syncthreads();
    float tot = s_red[0] + s_red[1] + s_red[2] + s_red[3];
    float scale = 1.0f / (fmaxf(sqrtf(tot), 1e-12f) * 8.0f);
    #pragma unroll
    for (int j = 0; j < 4; j++)
        out[((size_t)b * KCL + k) * CDIM + tid + 128 * j] = v[j] * scale;
}

// ---------------------------------------------------------------------------
extern "C" void kernel_launch(void* const* d_in, const int* in_sizes, int n_in,
                              void* d_out, int out_size)
{
    const float* x         = (const float*)d_in[0];
    const float* centroids = (const float*)d_in[1];
    const float* conv_w    = (const float*)d_in[2];
    const float* conv_b    = (const float*)d_in[3];
    float* out = (float*)d_out;

    cudaFuncSetAttribute(megapass, cudaFuncAttributeMaxDynamicSharedMemorySize, MP_SMEM);

    pass0w<<<1, 256>>>(conv_w);
    megapass<<<dim3(NTILES, BATCH), 256, MP_SMEM>>>(x, conv_b);
    pass3<<<dim3(KCL, BATCH), 128>>>(centroids, out);
}

// round 16
// speedup vs baseline: 1.4756x; 1.4756x over previous
#include <cuda_runtime.h>
#include <cuda_bf16.h>
#include <math.h>
#include <stdint.h>

#define BATCH 32
#define CDIM  512
#define NDIM  4096
#define TCL   72
#define KCL   64
#define NT1   128
#define NTILES 32            // 4096/128

// Scratch (static device globals; no runtime allocation)
__device__ __nv_bfloat16 g_a2h[(size_t)BATCH * KCL * NDIM];   // assign*invn, bf16
__device__ __nv_bfloat16 g_xb[(size_t)BATCH * CDIM * NDIM];   // x in bf16 (for pass2)
__device__ __nv_bfloat16 g_wb[16 * 80 * 32];                  // W bf16 [chunk16][t(80)][c(32)]
__device__ float g_massp[(size_t)BATCH * NTILES * KCL];
__device__ float g_agg[(size_t)BATCH * KCL * CDIM];

__device__ __forceinline__ unsigned smem_u32(const void* p) {
    unsigned a;
    asm("{ .reg .u64 t; cvta.to.shared.u64 t, %1; cvt.u32.u64 %0, t; }" : "=r"(a) : "l"(p));
    return a;
}
__device__ __forceinline__ void ldsm_x4(uint32_t* r, unsigned addr) {
    asm volatile("ldmatrix.sync.aligned.m8n8.x4.shared.b16 {%0,%1,%2,%3}, [%4];"
                 : "=r"(r[0]), "=r"(r[1]), "=r"(r[2]), "=r"(r[3]) : "r"(addr));
}
__device__ __forceinline__ void ldsm_x4t(uint32_t* r, unsigned addr) {
    asm volatile("ldmatrix.sync.aligned.m8n8.x4.trans.shared.b16 {%0,%1,%2,%3}, [%4];"
                 : "=r"(r[0]), "=r"(r[1]), "=r"(r[2]), "=r"(r[3]) : "r"(addr));
}
__device__ __forceinline__ void mma_bf16(float* c, const uint32_t* a, const uint32_t* b) {
    asm volatile(
        "mma.sync.aligned.m16n8k16.row.col.f32.bf16.bf16.f32 "
        "{%0,%1,%2,%3},{%4,%5,%6,%7},{%8,%9},{%0,%1,%2,%3};"
        : "+f"(c[0]), "+f"(c[1]), "+f"(c[2]), "+f"(c[3])
        : "r"(a[0]), "r"(a[1]), "r"(a[2]), "r"(a[3]), "r"(b[0]), "r"(b[1]));
}
__device__ __forceinline__ void sts_v2(unsigned addr, __nv_bfloat162 p0, __nv_bfloat162 p1) {
    asm volatile("st.shared.v2.b32 [%0], {%1,%2};"
                 :: "r"(addr), "r"(*(unsigned*)&p0), "r"(*(unsigned*)&p1));
}
__device__ __forceinline__ void cpa16(unsigned dst, const void* src) {
    asm volatile("cp.async.cg.shared.global [%0], [%1], 16;" :: "r"(dst), "l"(src));
}
#define CP_COMMIT() asm volatile("cp.async.commit_group;")

// ---------------------------------------------------------------------------
// Pass 0w: W fp32 -> bf16 table [16 chunks][80 t][32 c].
// PARALLEL: grid 160 x 256 threads, one element each (was grid 1: 22.7us!).
// ---------------------------------------------------------------------------
__global__ __launch_bounds__(256) void pass0w(const float* __restrict__ conv_w)
{
    const int i = blockIdx.x * 256 + threadIdx.x;   // 0..40959
    const int t = i >> 9, c = i & 511;
    float v = (t < TCL) ? conv_w[t * CDIM + c] : 0.0f;
    g_wb[(c >> 5) * 2560 + t * 32 + (c & 31)] = __float2bfloat16(v);
}

// ---------------------------------------------------------------------------
// Pass 1 (fused convert + HMMA GEMM + softmax), 2 blocks/SM:
// 4-stage cp.async (fp32 x 32c x 128n + W chunk 80t x 32c) -> convert (ssq,
// bf16 xbuf, g_xb writeout) -> MMA. Prefetch issued BEFORE convert.
// W smem tile rows stride 80B -> conflict-free ldmatrix, no swizzle.
// ---------------------------------------------------------------------------
#define P1_STG   23040u       // per stage: x 16384 (rows 512B) + W 6656 @ +16384
#define P1_WOFF  16384u
#define P1_XBUF  92160u       // 2 x (32c x 128n bf16, 256B rows, swz >>4)
#define P1_SSQS  108544u      // [8 cg][32 g][4] fp32 = 4KB (reused for mass parts)
#define P1_INVN  112640u      // 128 fp32
#define P1_BIAS  113152u      // 80 fp32
#define P1_SMEM  113472
#define P1_LG    0u           // phase B: [128 n][84 t] fp32 (43008B)
#define P1_A2ST  43008u       // [64 k][128 n] bf16 (16384B)

__global__ __launch_bounds__(256, 2) void pass1(const float* __restrict__ x,
                                                const float* __restrict__ conv_b)
{
    extern __shared__ char sm[];
    const unsigned sb = smem_u32(sm);
    const int ntile = blockIdx.x;
    const int b     = blockIdx.y;
    const int n0    = ntile * NT1;
    const int tid   = threadIdx.x;
    const int lane  = tid & 31;
    const int wid   = tid >> 5;
    const int m0    = wid * 16;

    if (tid < 80) {
        float v = (tid < TCL) ? conv_b[tid] : 0.0f;
        *(float*)(sm + P1_BIAS + tid * 4) = v;
    }

    const float* xsrc = x + (size_t)b * CDIM * NDIM + n0;

#define P1_ISSUE(ST, CH) do {                                                  \
        unsigned _buf = sb + (unsigned)(ST) * P1_STG;                          \
        const float* _xs = xsrc + (size_t)(CH) * 32 * NDIM;                    \
        _Pragma("unroll")                                                      \
        for (int r = 0; r < 4; r++) {                                          \
            int idx = tid + 256 * r;                                           \
            int c = idx >> 5, q = idx & 31;                                    \
            cpa16(_buf + (unsigned)(c * 512 + q * 16),                         \
                  _xs + (size_t)c * NDIM + 4 * q);                             \
        }                                                                      \
        const __nv_bfloat16* _ws = g_wb + (CH) * 2560;                         \
        _Pragma("unroll")                                                      \
        for (int r = 0; r < 2; r++) {                                          \
            int idx = tid + 256 * r;                                           \
            if (idx < 320) {                                                   \
                int t = idx >> 2, pc = idx & 3;                                \
                cpa16(_buf + P1_WOFF + (unsigned)(t * 80 + pc * 16),           \
                      _ws + t * 32 + pc * 8);                                  \
            }                                                                  \
        }                                                                      \
    } while (0)

    P1_ISSUE(0, 0); CP_COMMIT();
    P1_ISSUE(1, 1); CP_COMMIT();
    P1_ISSUE(2, 2); CP_COMMIT();

    float acc[10][4];
    #pragma unroll
    for (int i = 0; i < 10; i++)
        #pragma unroll
        for (int j = 0; j < 4; j++) acc[i][j] = 0.0f;
    float ssq4[4] = {0.f, 0.f, 0.f, 0.f};

    const int cg = tid >> 5;       // 0..7 (c sub-block of 4 rows)
    const int gq = tid & 31;       // float4 column (4 n)
    __nv_bfloat16* xbo = g_xb + (size_t)b * CDIM * NDIM + n0 + 4 * gq;

    for (int ch = 0; ch < 16; ch++) {
        asm volatile("cp.async.wait_group 2;" ::: "memory");
        __syncthreads();

        // prefetch issue FIRST: stage (ch+3)&3 == (ch-1)&3 was fully consumed
        // in chunk ch-1's convert -> safe, gains a convert-phase of lead.
        if (ch + 3 < 16) P1_ISSUE((ch + 3) & 3, ch + 3);
        CP_COMMIT();

        // convert: fp32 stage -> ssq + bf16 xbuf + g_xb
        {
            const char* stg = sm + (unsigned)(ch & 3) * P1_STG;
            const unsigned xbuf = sb + P1_XBUF + (unsigned)(ch & 1) * 8192u;
            #pragma unroll
            for (int r = 0; r < 4; r++) {
                int c = cg * 4 + r;
                float4 v = *(const float4*)(stg + c * 512 + gq * 16);
                ssq4[0] = fmaf(v.x, v.x, ssq4[0]);
                ssq4[1] = fmaf(v.y, v.y, ssq4[1]);
                ssq4[2] = fmaf(v.z, v.z, ssq4[2]);
                ssq4[3] = fmaf(v.w, v.w, ssq4[3]);
                __nv_bfloat162 h01 = __floats2bfloat162_rn(v.x, v.y);
                __nv_bfloat162 h23 = __floats2bfloat162_rn(v.z, v.w);
                unsigned off = (unsigned)(c * 256 + gq * 8);
                sts_v2(xbuf + (off ^ ((off >> 4) & 0x70)), h01, h23);
                uint2 u; u.x = *(unsigned*)&h01; u.y = *(unsigned*)&h23;
                *(uint2*)(xbo + (size_t)(ch * 32 + c) * NDIM) = u;
            }
        }
        __syncthreads();

        // MMA: 2 k-steps of 16 c over xbuf vs this chunk's W tile
        const unsigned xbuf = sb + P1_XBUF + (unsigned)(ch & 1) * 8192u;
        const unsigned wst  = sb + (unsigned)(ch & 3) * P1_STG + P1_WOFF;
        #pragma unroll
        for (int ks = 0; ks < 2; ks++) {
            uint32_t a[4];
            {   // A^T: [c][n] 256B rows; trans -> row-major n x c frags
                int crow = ks * 16 + (lane & 7) + ((lane >> 4) & 1) * 8;
                int ncol = m0 + ((lane >> 3) & 1) * 8;
                unsigned off = (unsigned)(crow * 256 + ncol * 2);
                ldsm_x4t(a, xbuf + (off ^ ((off >> 4) & 0x70)));
            }
            #pragma unroll
            for (int nb = 0; nb < 5; nb++) {
                uint32_t bf[4];
                int trow = nb * 16 + ((lane >> 4) & 1) * 8 + (lane & 7);
                unsigned addr = wst + (unsigned)(trow * 80 + ks * 32
                                                 + ((lane >> 3) & 1) * 16);
                ldsm_x4(bf, addr);    // stride-80B rows: conflict-free, no swz
                mma_bf16(acc[2 * nb],     a, &bf[0]);
                mma_bf16(acc[2 * nb + 1], a, &bf[2]);
            }
        }
    }

    // ssq partials -> invn (layout [cg][gq][4]; flat = tid*4)
    *(float4*)(sm + P1_SSQS + (unsigned)tid * 16) =
        make_float4(ssq4[0], ssq4[1], ssq4[2], ssq4[3]);
    __syncthreads();
    if (tid < 128) {
        const float* fs = (const float*)(sm + P1_SSQS);
        float s = 0.0f;
        #pragma unroll
        for (int w2 = 0; w2 < 8; w2++) s += fs[w2 * 128 + tid];
        ((float*)(sm + P1_INVN))[tid] = 1.0f / fmaxf(sqrtf(s), 1e-12f);
    }
    __syncthreads();

    // fragments -> logits smem [128 n][84 t]
    {
        float* lg = (float*)(sm + P1_LG);
        const float* invn = (const float*)(sm + P1_INVN);
        const float* bias = (const float*)(sm + P1_BIAS);
        int r0 = m0 + (lane >> 2);
        float i0 = invn[r0], i1 = invn[r0 + 8];
        #pragma unroll
        for (int nb = 0; nb < 10; nb++) {
            int tc = nb * 8 + 2 * (lane & 3);
            float b0 = bias[tc], b1 = bias[tc + 1];
            lg[r0 * 84 + tc]           = acc[nb][0] * i0 + b0;
            lg[r0 * 84 + tc + 1]       = acc[nb][1] * i0 + b1;
            lg[(r0 + 8) * 84 + tc]     = acc[nb][2] * i1 + b0;
            lg[(r0 + 8) * 84 + tc + 1] = acc[nb][3] * i1 + b1;
        }
    }
    __syncthreads();

    // softmax per n; a2 (bf16) into staging; assign stored for k<64 only
    if (tid < 128) {
        float* row = (float*)(sm + P1_LG) + tid * 84;
        float invn_n = ((float*)(sm + P1_INVN))[tid];
        float mx = -1e30f;
        #pragma unroll 8
        for (int t = 0; t < TCL; t++) mx = fmaxf(mx, row[t]);
        float s = 0.0f;
        #pragma unroll 8
        for (int t = 0; t < TCL; t++) { float e = __expf(row[t] - mx); row[t] = e; s += e; }
        float inv_s = 1.0f / s;
        float a2s   = inv_s * invn_n;
        __nv_bfloat16* a2st = (__nv_bfloat16*)(sm + P1_A2ST);
        #pragma unroll 8
        for (int t = 0; t < KCL; t++) {
            float e = row[t];
            a2st[t * 128 + tid] = __float2bfloat16(e * a2s);
            row[t] = e * inv_s;
        }
    }
    __syncthreads();

    // coalesced a2 writeout: [64 k][128 n] bf16 = 16KB
    #pragma unroll
    for (int it = 0; it < 4; it++) {
        int idx = tid + 256 * it;
        int k = idx >> 4, q2 = idx & 15;
        *(uint4*)((char*)(g_a2h + ((size_t)(b * KCL + k)) * NDIM + n0) + 16 * q2)
            = *(const uint4*)(sm + P1_A2ST + k * 256 + 16 * q2);
    }

    // mass partials, parallel over 256 threads: k = tid&63, part = tid>>6
    {
        float* mp = (float*)(sm + P1_SSQS);      // reuse (4KB free now)
        const float* lg = (const float*)(sm + P1_LG);
        const int k = tid & 63, part = tid >> 6;
        float m = 0.0f;
        #pragma unroll 8
        for (int n = 0; n < 32; n++) m += lg[(part * 32 + n) * 84 + k];
        mp[part * 64 + k] = m;
    }
    __syncthreads();
    if (tid < KCL) {
        const float* mp = (const float*)(sm + P1_SSQS);
        g_massp[((size_t)b * NTILES + ntile) * KCL + tid] =
            mp[tid] + mp[64 + tid] + mp[128 + tid] + mp[192 + tid];
    }
#undef P1_ISSUE
}

// ---------------------------------------------------------------------------
// Pass 2: HMMA bf16, 4-stage cp.async pipeline, no conversions.
// D[c,k] = sum_n xb[c,n]*a2[k,n]; M=128(c) N=64(k) K=4096(n), 64-n chunks.
// ---------------------------------------------------------------------------
#define STG_SZ 24576u
#define B_OFF  16384u

__global__ __launch_bounds__(256) void pass2()
{
    extern __shared__ char smem[];
    const unsigned sbase = smem_u32(smem);
    const int ct   = blockIdx.x;
    const int b    = blockIdx.y;
    const int c0   = ct * 128;
    const int tid  = threadIdx.x;
    const int lane = tid & 31;
    const int wid  = tid >> 5;
    const int warp_m = (wid & 3) * 32;
    const int warp_n = (wid >> 2) * 32;

    const __nv_bfloat16* xsrc = g_xb + ((size_t)b * CDIM + c0) * NDIM;
    const __nv_bfloat16* asrc = g_a2h + (size_t)b * KCL * NDIM;

#define P2_ISSUE(ST, CH) do {                                                  \
        unsigned _buf = sbase + (unsigned)(ST) * STG_SZ;                       \
        _Pragma("unroll")                                                      \
        for (int r = 0; r < 4; r++) {                                          \
            int g = tid + 256 * r; int row = g >> 3, c16 = g & 7;              \
            unsigned off = (unsigned)(row * 128 + c16 * 16);                   \
            cpa16(_buf + (off ^ ((off >> 3) & 0x70)),                          \
                  xsrc + (size_t)row * NDIM + (CH) * 64 + c16 * 8);            \
        }                                                                      \
        _Pragma("unroll")                                                      \
        for (int r = 0; r < 2; r++) {                                          \
            int g = tid + 256 * r; int k = g >> 3, c16 = g & 7;                \
            unsigned off = (unsigned)(k * 128 + c16 * 16);                     \
            cpa16(_buf + B_OFF + (off ^ ((off >> 3) & 0x70)),                  \
                  asrc + (size_t)k * NDIM + (CH) * 64 + c16 * 8);              \
        }                                                                      \
    } while (0)

    P2_ISSUE(0, 0); CP_COMMIT();
    P2_ISSUE(1, 1); CP_COMMIT();
    P2_ISSUE(2, 2); CP_COMMIT();

    float acc[2][4][4];
    #pragma unroll
    for (int i = 0; i < 2; i++)
        #pragma unroll
        for (int j = 0; j < 4; j++)
            #pragma unroll
            for (int q = 0; q < 4; q++) acc[i][j][q] = 0.0f;

    for (int ch = 0; ch < 64; ch++) {
        asm volatile("cp.async.wait_group 2;" ::: "memory");
        __syncthreads();
        if (ch + 3 < 64) P2_ISSUE((ch + 3) & 3, ch + 3);
        CP_COMMIT();

        const unsigned buf = sbase + (unsigned)(ch & 3) * STG_SZ;
        #pragma unroll
        for (int ks = 0; ks < 4; ks++) {
            uint32_t ah[2][4], bh2[2][4];
            #pragma unroll
            for (int mf = 0; mf < 2; mf++) {
                unsigned off = (unsigned)((warp_m + mf * 16 + (lane & 15)) * 128
                                          + ks * 32 + (lane >> 4) * 16);
                ldsm_x4(ah[mf], buf + (off ^ ((off >> 3) & 0x70)));
            }
            #pragma unroll
            for (int np = 0; np < 2; np++) {
                unsigned off = (unsigned)((warp_n + np * 16 + (lane >> 4) * 8 + (lane & 7)) * 128
                                          + ks * 32 + ((lane >> 3) & 1) * 16);
                ldsm_x4(bh2[np], buf + B_OFF + (off ^ ((off >> 3) & 0x70)));
            }
            #pragma unroll
            for (int mf = 0; mf < 2; mf++)
                #pragma unroll
                for (int np = 0; np < 2; np++)
                    #pragma unroll
                    for (int h = 0; h < 2; h++)
                        mma_bf16(acc[mf][np * 2 + h], ah[mf], &bh2[np][2 * h]);
        }
    }

    const int bbase = b * KCL;
    #pragma unroll
    for (int mf = 0; mf < 2; mf++) {
        int row = c0 + warp_m + mf * 16 + (lane >> 2);
        #pragma unroll
        for (int nf = 0; nf < 4; nf++) {
            int k = warp_n + nf * 8 + (lane & 3) * 2;
            float* g0 = g_agg + (size_t)(bbase + k) * CDIM + row;
            g0[0]        = acc[mf][nf][0];
            g0[CDIM]     = acc[mf][nf][1];
            g0[8]        = acc[mf][nf][2];
            g0[CDIM + 8] = acc[mf][nf][3];
        }
    }
#undef P2_ISSUE
}

// ---------------------------------------------------------------------------
// Pass 3: v = agg - centroid*mass; out = v/(max(||v||,eps)*8)
// (attention, ghost weighting and global norm cancel algebraically)
// ---------------------------------------------------------------------------
__global__ __launch_bounds__(128) void pass3(const float* __restrict__ centroids,
                                             float* __restrict__ out)
{
    const int k   = blockIdx.x;
    const int b   = blockIdx.y;
    const int tid = threadIdx.x;

    __shared__ float s_mass;
    __shared__ float s_red[4];

    if (tid == 0) {
        float m = 0.0f;
        #pragma unroll
        for (int t = 0; t < NTILES; t++) m += g_massp[((size_t)b * NTILES + t) * KCL + k];
        s_mass = m;
    }
    __syncthreads();
    const float mass = s_mass;

    float v[4];
    float ssq = 0.0f;
    #pragma unroll
    for (int j = 0; j < 4; j++) {
        int c = tid + 128 * j;
        float val = g_agg[((size_t)b * KCL + k) * CDIM + c] - centroids[k * CDIM + c] * mass;
        v[j] = val;
        ssq = fmaf(val, val, ssq);
    }
    #pragma unroll
    for (int o = 16; o > 0; o >>= 1) ssq += __shfl_xor_sync(0xffffffffu, ssq, o);
    if ((tid & 31) == 0) s_red[tid >> 5] = ssq;
    __syncthreads();
    float tot = s_red[0] + s_red[1] + s_red[2] + s_red[3];
    float scale = 1.0f / (fmaxf(sqrtf(tot), 1e-12f) * 8.0f);
    #pragma unroll
    for (int j = 0; j < 4; j++)
        out[((size_t)b * KCL + k) * CDIM + tid + 128 * j] = v[j] * scale;
}

// ---------------------------------------------------------------------------
extern "C" void kernel_launch(void* const* d_in, const int* in_sizes, int n_in,
                              void* d_out, int out_size)
{
    const float* x         = (const float*)d_in[0];
    const float* centroids = (const float*)d_in[1];
    const float* conv_w    = (const float*)d_in[2];
    const float* conv_b    = (const float*)d_in[3];
    float* out = (float*)d_out;

    cudaFuncSetAttribute(pass1, cudaFuncAttributeMaxDynamicSharedMemorySize, P1_SMEM);
    cudaFuncSetAttribute(pass2, cudaFuncAttributeMaxDynamicSharedMemorySize, 98304);

    pass0w<<<160, 256>>>(conv_w);
    pass1<<<dim3(NTILES, BATCH), 256, P1_SMEM>>>(x, conv_b);
    pass2<<<dim3(4, BATCH), 256, 98304>>>();
    pass3<<<dim3(KCL, BATCH), 128>>>(centroids, out);
}